// round 1
// baseline (speedup 1.0000x reference)
#include <cuda_runtime.h>

#define Bc   4
#define Hc   512
#define Wc   229
#define Cc   32
#define OUTc 88
#define FRAME_ELEMS (Bc*Hc*OUTc)     /* 180224 */
#define NROW (Bc*Hc)                 /* 2048 */
#define RB   16                      /* rows per block in kernel C */

__device__ float g_ov[NROW*Wc];      // Σ_k attn_k * nb_k per pixel
__device__ float g_weff[OUTc*Wc];    // folded linear weights
__device__ float g_scal[8];          // [0]=A, [1..3]=Rt, [4..6]=Rf

// ---------------------------------------------------------------------------
// Kernel A: precompute scalars A, Rt[3], Rf[3] and Weff[88][229]
// ---------------------------------------------------------------------------
__global__ void kA(const float* __restrict__ Wq, const float* __restrict__ Wk,
                   const float* __restrict__ Wv, const float* __restrict__ rel_t,
                   const float* __restrict__ rel_f, const float* __restrict__ W_lin)
{
    int o = blockIdx.x, t = threadIdx.x;

    if (o == 0 && t >= Wc) {                   // spare threads do the scalars
        int j = t - Wc;
        if (j == 0) {
            float a = 0.f;
            #pragma unroll
            for (int c = 0; c < Cc; c++) a += Wq[c] * Wk[c];
            g_scal[0] = a;
        } else if (j >= 1 && j <= 3) {
            int kt = j - 1; float r = 0.f;
            #pragma unroll
            for (int c = 0; c < 16; c++) r += Wq[c] * rel_t[c*3 + kt];
            g_scal[1 + kt] = r;
        } else if (j >= 4 && j <= 6) {
            int kf = j - 4; float r = 0.f;
            #pragma unroll
            for (int c = 0; c < 16; c++) r += Wq[16 + c] * rel_f[c*3 + kf];
            g_scal[4 + kf] = r;
        }
    }
    if (t < Wc) {
        float acc = 0.f;
        #pragma unroll
        for (int c = 0; c < Cc; c++)
            acc += W_lin[o*(Cc*Wc) + c*Wc + t] * Wv[c];
        g_weff[o*Wc + t] = acc;
    }
}

// ---------------------------------------------------------------------------
// fast exp(d) for d <= 0 : FMA-pipe exp2 poly (avoids MUFU throughput limit)
// max rel err ~2e-6
// ---------------------------------------------------------------------------
__device__ __forceinline__ float fexp_neg(float d)
{
    float y = d * 1.4426950408889634f;   // log2(e)
    float r = rintf(y);
    float f = y - r;                      // f in [-0.5, 0.5]
    float p = 1.3333558146e-3f;
    p = fmaf(p, f, 9.6181291076e-3f);
    p = fmaf(p, f, 5.5504108665e-2f);
    p = fmaf(p, f, 2.4022650696e-1f);
    p = fmaf(p, f, 6.9314718056e-1f);
    p = fmaf(p, f, 1.0f);
    int ri = (int)r;
    if (ri < -126) ri = -126;
    return p * __int_as_float((ri + 127) << 23);
}

// ---------------------------------------------------------------------------
// Kernel B: per-pixel 9-way softmax, writes attn (bulk of output) + ov scratch
// one block per (b,h) row; 229 active lanes
// ---------------------------------------------------------------------------
__global__ void kB(const float* __restrict__ spec, float* __restrict__ out_attn)
{
    int blk = blockIdx.x;
    int b = blk >> 9, h = blk & 511;
    __shared__ float sh[3][232];          // 3 rows with +/-1 col halo
    int t = threadIdx.x;

    for (int i = t; i < 3*231; i += 256) {
        int row = i / 231, c = i % 231 - 1;
        int gh = h - 1 + row;
        float v = 0.f;
        if (gh >= 0 && gh < Hc && c >= 0 && c < Wc)
            v = spec[(b*Hc + gh)*Wc + c];
        sh[row][i % 231] = v;
    }
    __syncthreads();
    if (t >= Wc) return;

    const float A   = g_scal[0];
    const float Rt[3] = { g_scal[1], g_scal[2], g_scal[3] };
    const float Rf[3] = { g_scal[4], g_scal[5], g_scal[6] };

    float s = sh[1][t + 1];
    float nb[9], e[9];
    #pragma unroll
    for (int kt = 0; kt < 3; kt++)
        #pragma unroll
        for (int kf = 0; kf < 3; kf++) {
            float n = sh[kt][t + kf];
            nb[kt*3 + kf] = n;
            e[kt*3 + kf]  = s * fmaf(A, n, Rt[kt] + Rf[kf]);
        }

    float m = e[0];
    #pragma unroll
    for (int k = 1; k < 9; k++) m = fmaxf(m, e[k]);

    float p[9], sum = 0.f;
    #pragma unroll
    for (int k = 0; k < 9; k++) { p[k] = fexp_neg(e[k] - m); sum += p[k]; }
    float rinv = __fdividef(1.f, sum);

    int   base = (blk*Wc + t) * 9;
    float ov = 0.f;
    #pragma unroll
    for (int k = 0; k < 9; k++) {
        float a = p[k] * rinv;
        out_attn[base + k] = a;
        ov = fmaf(a, nb[k], ov);
    }
    g_ov[blk*Wc + t] = ov;
}

// ---------------------------------------------------------------------------
// Kernel C: frame_pred = sigmoid(ov @ Weff^T + b)
// 16 rows/block, full Weff in smem (95 KB dyn), 4x2 register tile,
// float4 load of transposed ov slab
// ---------------------------------------------------------------------------
__global__ void kC(const float* __restrict__ b_lin, float* __restrict__ out_frame)
{
    extern __shared__ float sm[];
    float* s_w  = sm;                  // [88*229]
    float* s_ov = sm + OUTc*Wc;        // transposed [229][16]
    int t  = threadIdx.x;
    int rb = blockIdx.x * RB;

    for (int i = t; i < OUTc*Wc; i += blockDim.x) s_w[i] = g_weff[i];
    for (int i = t; i < RB*Wc;   i += blockDim.x) {
        int r = i / Wc, w = i % Wc;
        s_ov[w*RB + r] = g_ov[(rb + r)*Wc + w];
    }
    __syncthreads();
    if (t >= 176) return;

    int og = t % 44, rg = t / 44;          // 44 o-pairs x 4 row-quads
    int o0 = og * 2, o1 = o0 + 1;
    const float* w0p = s_w + o0*Wc;
    const float* w1p = s_w + o1*Wc;

    float acc[4][2] = {};
    for (int w = 0; w < Wc; w++) {
        float4 ov = *(const float4*)&s_ov[w*RB + rg*4];
        float w0 = w0p[w], w1 = w1p[w];
        acc[0][0] = fmaf(ov.x, w0, acc[0][0]); acc[0][1] = fmaf(ov.x, w1, acc[0][1]);
        acc[1][0] = fmaf(ov.y, w0, acc[1][0]); acc[1][1] = fmaf(ov.y, w1, acc[1][1]);
        acc[2][0] = fmaf(ov.z, w0, acc[2][0]); acc[2][1] = fmaf(ov.z, w1, acc[2][1]);
        acc[3][0] = fmaf(ov.w, w0, acc[3][0]); acc[3][1] = fmaf(ov.w, w1, acc[3][1]);
    }

    float bb0 = b_lin[o0], bb1 = b_lin[o1];
    #pragma unroll
    for (int i = 0; i < 4; i++) {
        int row = rb + rg*4 + i;
        float v0 = acc[i][0] + bb0;
        float v1 = acc[i][1] + bb1;
        out_frame[row*OUTc + o0] = __fdividef(1.f, 1.f + __expf(-v0));
        out_frame[row*OUTc + o1] = __fdividef(1.f, 1.f + __expf(-v1));
    }
}

// ---------------------------------------------------------------------------
extern "C" void kernel_launch(void* const* d_in, const int* in_sizes, int n_in,
                              void* d_out, int out_size)
{
    const float* spec  = (const float*)d_in[0];
    const float* Wq    = (const float*)d_in[1];
    const float* Wk    = (const float*)d_in[2];
    const float* Wv    = (const float*)d_in[3];
    const float* rel_t = (const float*)d_in[4];
    const float* rel_f = (const float*)d_in[5];
    const float* W_lin = (const float*)d_in[6];
    const float* b_lin = (const float*)d_in[7];
    float* out = (float*)d_out;

    const int smemC = (OUTc*Wc + RB*Wc) * (int)sizeof(float);   // 95264 B
    cudaFuncSetAttribute(kC, cudaFuncAttributeMaxDynamicSharedMemorySize, smemC);

    kA<<<OUTc, 256>>>(Wq, Wk, Wv, rel_t, rel_f, W_lin);
    kB<<<NROW, 256>>>(spec, out + FRAME_ELEMS);
    kC<<<NROW/RB, 192, smemC>>>(b_lin, out);
}

// round 2
// speedup vs baseline: 1.3361x; 1.3361x over previous
#include <cuda_runtime.h>

#define Bc   4
#define Hc   512
#define Wc   229
#define Cc   32
#define OUTc 88
#define FRAME_ELEMS (Bc*Hc*OUTc)     /* 180224 */
#define NROW (Bc*Hc)                 /* 2048 */
#define RB   16                      /* rows per block in kernel C */
#define OVP  233                     /* padded ov row stride (conflict-free) */

__device__ float g_ov[NROW*Wc];       // Σ_k attn_k * nb_k per pixel
__device__ float g_wT[Wc*OUTc];       // folded linear weights, transposed [w][o]
__device__ float g_scal[8];           // [0]=A, [1..3]=Rt, [4..6]=Rf

// ---------------------------------------------------------------------------
// Kernel A: precompute scalars A, Rt[3], Rf[3] and WeffT[229][88]
// 88 blocks x 1024 threads: 4 channel-groups of 8, smem reduction
// ---------------------------------------------------------------------------
__global__ void kA(const float* __restrict__ Wq, const float* __restrict__ Wk,
                   const float* __restrict__ Wv, const float* __restrict__ rel_t,
                   const float* __restrict__ rel_f, const float* __restrict__ W_lin)
{
    __shared__ float part[4][240];
    int o  = blockIdx.x;
    int t  = threadIdx.x;
    int g  = t >> 8;        // channel group 0..3
    int tt = t & 255;       // w lane

    if (o == 0 && g == 3 && tt >= Wc && tt < Wc + 7) {   // spare threads: scalars
        int j = tt - Wc;
        if (j == 0) {
            float a = 0.f;
            #pragma unroll
            for (int c = 0; c < Cc; c++) a += Wq[c] * Wk[c];
            g_scal[0] = a;
        } else if (j <= 3) {
            int kt = j - 1; float r = 0.f;
            #pragma unroll
            for (int c = 0; c < 16; c++) r += Wq[c] * rel_t[c*3 + kt];
            g_scal[1 + kt] = r;
        } else {
            int kf = j - 4; float r = 0.f;
            #pragma unroll
            for (int c = 0; c < 16; c++) r += Wq[16 + c] * rel_f[c*3 + kf];
            g_scal[4 + kf] = r;
        }
    }

    float acc = 0.f;
    if (tt < Wc) {
        const float* base = W_lin + o*(Cc*Wc) + (g*8)*Wc + tt;
        #pragma unroll
        for (int c = 0; c < 8; c++)
            acc = fmaf(base[c*Wc], Wv[g*8 + c], acc);
        part[g][tt] = acc;
    }
    __syncthreads();
    if (g == 0 && tt < Wc)
        g_wT[tt*OUTc + o] = part[0][tt] + part[1][tt] + part[2][tt] + part[3][tt];
}

// ---------------------------------------------------------------------------
// fast exp(d), d <= 0 : FMA-pipe exp2 poly + magic-number round
// max rel err ~2e-6
// ---------------------------------------------------------------------------
__device__ __forceinline__ float fexp_neg(float d)
{
    const float L2E   = 1.4426950408889634f;
    const float MAGIC = 12582912.0f;              // 1.5 * 2^23
    float t0 = fmaf(d, L2E, MAGIC);
    float r  = t0 - MAGIC;
    float f  = fmaf(d, L2E, -r);                  // f in [-0.5, 0.5]
    float p = 1.3333558146e-3f;
    p = fmaf(p, f, 9.6181291076e-3f);
    p = fmaf(p, f, 5.5504108665e-2f);
    p = fmaf(p, f, 2.4022650696e-1f);
    p = fmaf(p, f, 6.9314718056e-1f);
    p = fmaf(p, f, 1.0f);
    int ri = __float_as_int(t0) - 0x4B400000;     // integer round of d*log2(e)
    ri = ri < -126 ? -126 : ri;
    return p * __int_as_float((ri + 127) << 23);
}

// ---------------------------------------------------------------------------
// Kernel B: per-pixel 9-way softmax; attn staged in smem then coalesced store
// one block per (b,h) row; 229 active compute lanes, 256 store lanes
// ---------------------------------------------------------------------------
__global__ void kB(const float* __restrict__ spec, float* __restrict__ out_attn)
{
    int blk = blockIdx.x;
    int b = blk >> 9, h = blk & 511;
    __shared__ float sh[3][232];            // 3 rows with +/-1 col halo
    __shared__ float sh_attn[Wc*9];         // 2061 floats
    int t = threadIdx.x;

    for (int i = t; i < 3*231; i += 256) {
        int row = i / 231, c = i % 231 - 1;
        int gh = h - 1 + row;
        float v = 0.f;
        if (gh >= 0 && gh < Hc && c >= 0 && c < Wc)
            v = spec[(b*Hc + gh)*Wc + c];
        sh[row][i % 231] = v;
    }
    __syncthreads();

    if (t < Wc) {
        const float A = g_scal[0];
        const float Rt[3] = { g_scal[1], g_scal[2], g_scal[3] };
        const float Rf[3] = { g_scal[4], g_scal[5], g_scal[6] };

        float s  = sh[1][t + 1];
        float sA = s * A;
        float nb[9], e[9];
        #pragma unroll
        for (int kt = 0; kt < 3; kt++) {
            float sr = s * Rt[kt];
            #pragma unroll
            for (int kf = 0; kf < 3; kf++) {
                float n = sh[kt][t + kf];
                nb[kt*3 + kf] = n;
                e[kt*3 + kf]  = fmaf(sA, n, fmaf(s, Rf[kf], sr));
            }
        }

        float m = e[0];
        #pragma unroll
        for (int k = 1; k < 9; k++) m = fmaxf(m, e[k]);

        float p[9], sum = 0.f;
        #pragma unroll
        for (int k = 0; k < 9; k++) { p[k] = fexp_neg(e[k] - m); sum += p[k]; }
        float rinv = __fdividef(1.f, sum);

        float ov = 0.f;
        #pragma unroll
        for (int k = 0; k < 9; k++) {
            float a = p[k] * rinv;
            sh_attn[t*9 + k] = a;            // stride 9 -> conflict-free
            ov = fmaf(a, nb[k], ov);
        }
        g_ov[blk*Wc + t] = ov;
    }
    __syncthreads();

    float* dst = out_attn + blk*(Wc*9);
    for (int i = t; i < Wc*9; i += 256)      // fully coalesced writeback
        dst[i] = sh_attn[i];
}

// ---------------------------------------------------------------------------
// Kernel C: frame_pred = sigmoid(ov @ Weff^T + b)
// 128 blocks x 256 threads, 16 rows/block, Weff^T + ov row-major in smem.
// Per compute thread (176 active): 2 rows x 4 outs, float4 weight loads.
// ---------------------------------------------------------------------------
__global__ void kC(const float* __restrict__ b_lin, float* __restrict__ out_frame)
{
    extern __shared__ float sm[];
    float* s_wT = sm;                       // [229][88]
    float* s_ov = sm + Wc*OUTc;             // [16][233]
    int t  = threadIdx.x;
    int rb = blockIdx.x * RB;

    // Weff^T copy (contiguous, float4)
    {
        const float4* src = (const float4*)g_wT;
        float4* dst = (float4*)s_wT;
        for (int i = t; i < (Wc*OUTc)/4; i += 256) dst[i] = src[i];
    }
    // ov slab, row-major with pad 233 (coalesced read, conflict-free use)
    for (int i = t; i < RB*Wc; i += 256) {
        int r = i / Wc, w = i - r*Wc;
        s_ov[r*OVP + w] = g_ov[(rb + r)*Wc + w];
    }
    __syncthreads();
    if (t >= 176) return;

    int rg = t & 7;                          // row pair 0..7
    int og = t >> 3;                         // out quad 0..21
    const float* wq   = s_wT + og*4;
    const float* ovr0 = s_ov + (rg*2)*OVP;
    const float* ovr1 = ovr0 + OVP;

    float4 acc0 = {0.f,0.f,0.f,0.f};
    float4 acc1 = {0.f,0.f,0.f,0.f};
    #pragma unroll 4
    for (int w = 0; w < Wc; w++) {
        float4 wv = *(const float4*)(wq + w*OUTc);
        float a0 = ovr0[w], a1 = ovr1[w];
        acc0.x = fmaf(a0, wv.x, acc0.x); acc0.y = fmaf(a0, wv.y, acc0.y);
        acc0.z = fmaf(a0, wv.z, acc0.z); acc0.w = fmaf(a0, wv.w, acc0.w);
        acc1.x = fmaf(a1, wv.x, acc1.x); acc1.y = fmaf(a1, wv.y, acc1.y);
        acc1.z = fmaf(a1, wv.z, acc1.z); acc1.w = fmaf(a1, wv.w, acc1.w);
    }

    float4 bb = *(const float4*)&b_lin[og*4];
    float4 r0, r1;
    r0.x = __fdividef(1.f, 1.f + __expf(-(acc0.x + bb.x)));
    r0.y = __fdividef(1.f, 1.f + __expf(-(acc0.y + bb.y)));
    r0.z = __fdividef(1.f, 1.f + __expf(-(acc0.z + bb.z)));
    r0.w = __fdividef(1.f, 1.f + __expf(-(acc0.w + bb.w)));
    r1.x = __fdividef(1.f, 1.f + __expf(-(acc1.x + bb.x)));
    r1.y = __fdividef(1.f, 1.f + __expf(-(acc1.y + bb.y)));
    r1.z = __fdividef(1.f, 1.f + __expf(-(acc1.z + bb.z)));
    r1.w = __fdividef(1.f, 1.f + __expf(-(acc1.w + bb.w)));

    int row0 = rb + rg*2;
    *(float4*)&out_frame[row0*OUTc + og*4]       = r0;
    *(float4*)&out_frame[(row0 + 1)*OUTc + og*4] = r1;
}

// ---------------------------------------------------------------------------
extern "C" void kernel_launch(void* const* d_in, const int* in_sizes, int n_in,
                              void* d_out, int out_size)
{
    const float* spec  = (const float*)d_in[0];
    const float* Wq    = (const float*)d_in[1];
    const float* Wk    = (const float*)d_in[2];
    const float* Wv    = (const float*)d_in[3];
    const float* rel_t = (const float*)d_in[4];
    const float* rel_f = (const float*)d_in[5];
    const float* W_lin = (const float*)d_in[6];
    const float* b_lin = (const float*)d_in[7];
    float* out = (float*)d_out;

    const int smemC = (Wc*OUTc + RB*OVP) * (int)sizeof(float);   // ~95.5 KB
    cudaFuncSetAttribute(kC, cudaFuncAttributeMaxDynamicSharedMemorySize, smemC);

    kA<<<OUTc, 1024>>>(Wq, Wk, Wv, rel_t, rel_f, W_lin);
    kB<<<NROW, 256>>>(spec, out + FRAME_ELEMS);
    kC<<<NROW/RB, 256, smemC>>>(b_lin, out);
}

// round 3
// speedup vs baseline: 1.4314x; 1.0714x over previous
#include <cuda_runtime.h>

#define Bc   4
#define Hc   512
#define Wc   229
#define Cc   32
#define OUTc 88
#define FRAME_ELEMS (Bc*Hc*OUTc)     /* 180224 */
#define NROW (Bc*Hc)                 /* 2048 */
#define RB   16                      /* rows per block in kernel C */
#define OVP  233                     /* padded ov row stride (conflict-free) */

__device__ float g_ov[NROW*Wc];       // Σ_k attn_k * nb_k per pixel
__device__ float g_wT[Wc*OUTc];       // folded linear weights, transposed [w][o]

// ---------------------------------------------------------------------------
// fast exp(d), d <= 0 : FMA-pipe exp2 poly + magic-number round
// ---------------------------------------------------------------------------
__device__ __forceinline__ float fexp_neg(float d)
{
    const float L2E   = 1.4426950408889634f;
    const float MAGIC = 12582912.0f;              // 1.5 * 2^23
    float t0 = fmaf(d, L2E, MAGIC);
    float r  = t0 - MAGIC;
    float f  = fmaf(d, L2E, -r);                  // f in [-0.5, 0.5]
    float p = 1.3333558146e-3f;
    p = fmaf(p, f, 9.6181291076e-3f);
    p = fmaf(p, f, 5.5504108665e-2f);
    p = fmaf(p, f, 2.4022650696e-1f);
    p = fmaf(p, f, 6.9314718056e-1f);
    p = fmaf(p, f, 1.0f);
    int ri = __float_as_int(t0) - 0x4B400000;     // integer round of d*log2(e)
    ri = ri < -126 ? -126 : ri;
    return p * __int_as_float((ri + 127) << 23);
}

// ---------------------------------------------------------------------------
// K1: per-(b,h)-row softmax + attn + ov. Scalars computed inline per block.
// Blocks 0..87 additionally fold W_lin -> WeffT column (tail work).
// ---------------------------------------------------------------------------
__global__ void k1(const float* __restrict__ spec,
                   const float* __restrict__ Wq,  const float* __restrict__ Wk,
                   const float* __restrict__ Wv,  const float* __restrict__ rel_t,
                   const float* __restrict__ rel_f, const float* __restrict__ W_lin,
                   float* __restrict__ out_attn)
{
    int blk = blockIdx.x;
    int b = blk >> 9, h = blk & 511;
    __shared__ float sh[3][232];            // 3 rows with +/-1 col halo
    __shared__ float sh_attn[Wc*9];         // 2061 floats
    __shared__ float s_scal[7];
    int t = threadIdx.x;

    // threads 0..6: per-block scalar precompute (tiny tensors, L2-hot)
    if (t < 7) {
        if (t == 0) {
            float a = 0.f;
            #pragma unroll
            for (int c = 0; c < Cc; c++) a = fmaf(Wq[c], Wk[c], a);
            s_scal[0] = a;
        } else if (t <= 3) {
            int kt = t - 1; float r = 0.f;
            #pragma unroll
            for (int c = 0; c < 16; c++) r = fmaf(Wq[c], rel_t[c*3 + kt], r);
            s_scal[t] = r;
        } else {
            int kf = t - 4; float r = 0.f;
            #pragma unroll
            for (int c = 0; c < 16; c++) r = fmaf(Wq[16 + c], rel_f[c*3 + kf], r);
            s_scal[t] = r;
        }
    }

    // halo tile load (3 rows x 231 cols)
    for (int i = t; i < 3*231; i += 256) {
        int row = i / 231, c = i % 231 - 1;
        int gh = h - 1 + row;
        float v = 0.f;
        if (gh >= 0 && gh < Hc && c >= 0 && c < Wc)
            v = spec[(b*Hc + gh)*Wc + c];
        sh[row][i % 231] = v;
    }
    __syncthreads();

    if (t < Wc) {
        const float A = s_scal[0];
        const float Rt[3] = { s_scal[1], s_scal[2], s_scal[3] };
        const float Rf[3] = { s_scal[4], s_scal[5], s_scal[6] };

        float s  = sh[1][t + 1];
        float sA = s * A;
        float nb[9], e[9];
        #pragma unroll
        for (int kt = 0; kt < 3; kt++) {
            float sr = s * Rt[kt];
            #pragma unroll
            for (int kf = 0; kf < 3; kf++) {
                float n = sh[kt][t + kf];
                nb[kt*3 + kf] = n;
                e[kt*3 + kf]  = fmaf(sA, n, fmaf(s, Rf[kf], sr));
            }
        }

        float m = e[0];
        #pragma unroll
        for (int k = 1; k < 9; k++) m = fmaxf(m, e[k]);

        float p[9], sum = 0.f;
        #pragma unroll
        for (int k = 0; k < 9; k++) { p[k] = fexp_neg(e[k] - m); sum += p[k]; }
        float rinv = __fdividef(1.f, sum);

        float ov = 0.f;
        #pragma unroll
        for (int k = 0; k < 9; k++) {
            float a = p[k] * rinv;
            sh_attn[t*9 + k] = a;            // stride 9 -> conflict-free
            ov = fmaf(a, nb[k], ov);
        }
        g_ov[blk*Wc + t] = ov;
    }
    __syncthreads();

    float* dst = out_attn + blk*(Wc*9);
    for (int i = t; i < Wc*9; i += 256)      // coalesced writeback
        dst[i] = sh_attn[i];

    // tail work: blocks 0..87 fold one WeffT column (o = blk)
    if (blk < OUTc && t < Wc) {
        const float* base = W_lin + blk*(Cc*Wc) + t;
        float acc = 0.f;
        #pragma unroll
        for (int c = 0; c < Cc; c++)
            acc = fmaf(base[c*Wc], Wv[c], acc);
        g_wT[t*OUTc + blk] = acc;
    }
}

// ---------------------------------------------------------------------------
// K2: frame_pred = sigmoid(ov @ Weff^T + b)
// 128 blocks x 256 threads, 16 rows/block, Weff^T + ov row-major in smem.
// Per compute thread (176 active): 2 rows x 4 outs, float4 weight loads.
// ---------------------------------------------------------------------------
__global__ void k2(const float* __restrict__ b_lin, float* __restrict__ out_frame)
{
    extern __shared__ float sm[];
    float* s_wT = sm;                       // [229][88]
    float* s_ov = sm + Wc*OUTc;             // [16][233]
    int t  = threadIdx.x;
    int rb = blockIdx.x * RB;

    {
        const float4* src = (const float4*)g_wT;
        float4* dst = (float4*)s_wT;
        for (int i = t; i < (Wc*OUTc)/4; i += 256) dst[i] = src[i];
    }
    for (int i = t; i < RB*Wc; i += 256) {
        int r = i / Wc, w = i - r*Wc;
        s_ov[r*OVP + w] = g_ov[(rb + r)*Wc + w];
    }
    __syncthreads();
    if (t >= 176) return;

    int rg = t & 7;                          // row pair 0..7
    int og = t >> 3;                         // out quad 0..21
    const float* wq   = s_wT + og*4;
    const float* ovr0 = s_ov + (rg*2)*OVP;
    const float* ovr1 = ovr0 + OVP;

    float4 acc0 = {0.f,0.f,0.f,0.f};
    float4 acc1 = {0.f,0.f,0.f,0.f};
    #pragma unroll 4
    for (int w = 0; w < Wc; w++) {
        float4 wv = *(const float4*)(wq + w*OUTc);
        float a0 = ovr0[w], a1 = ovr1[w];
        acc0.x = fmaf(a0, wv.x, acc0.x); acc0.y = fmaf(a0, wv.y, acc0.y);
        acc0.z = fmaf(a0, wv.z, acc0.z); acc0.w = fmaf(a0, wv.w, acc0.w);
        acc1.x = fmaf(a1, wv.x, acc1.x); acc1.y = fmaf(a1, wv.y, acc1.y);
        acc1.z = fmaf(a1, wv.z, acc1.z); acc1.w = fmaf(a1, wv.w, acc1.w);
    }

    float4 bb = *(const float4*)&b_lin[og*4];
    float4 r0, r1;
    r0.x = __fdividef(1.f, 1.f + __expf(-(acc0.x + bb.x)));
    r0.y = __fdividef(1.f, 1.f + __expf(-(acc0.y + bb.y)));
    r0.z = __fdividef(1.f, 1.f + __expf(-(acc0.z + bb.z)));
    r0.w = __fdividef(1.f, 1.f + __expf(-(acc0.w + bb.w)));
    r1.x = __fdividef(1.f, 1.f + __expf(-(acc1.x + bb.x)));
    r1.y = __fdividef(1.f, 1.f + __expf(-(acc1.y + bb.y)));
    r1.z = __fdividef(1.f, 1.f + __expf(-(acc1.z + bb.z)));
    r1.w = __fdividef(1.f, 1.f + __expf(-(acc1.w + bb.w)));

    int row0 = rb + rg*2;
    *(float4*)&out_frame[row0*OUTc + og*4]       = r0;
    *(float4*)&out_frame[(row0 + 1)*OUTc + og*4] = r1;
}

// ---------------------------------------------------------------------------
extern "C" void kernel_launch(void* const* d_in, const int* in_sizes, int n_in,
                              void* d_out, int out_size)
{
    const float* spec  = (const float*)d_in[0];
    const float* Wq    = (const float*)d_in[1];
    const float* Wk    = (const float*)d_in[2];
    const float* Wv    = (const float*)d_in[3];
    const float* rel_t = (const float*)d_in[4];
    const float* rel_f = (const float*)d_in[5];
    const float* W_lin = (const float*)d_in[6];
    const float* b_lin = (const float*)d_in[7];
    float* out = (float*)d_out;

    const int smemC = (Wc*OUTc + RB*OVP) * (int)sizeof(float);   // ~95.5 KB
    cudaFuncSetAttribute(k2, cudaFuncAttributeMaxDynamicSharedMemorySize, smemC);

    k1<<<NROW, 256>>>(spec, Wq, Wk, Wv, rel_t, rel_f, W_lin, out + FRAME_ELEMS);
    k2<<<NROW/RB, 256, smemC>>>(b_lin, out);
}

// round 4
// speedup vs baseline: 1.6633x; 1.1620x over previous
#include <cuda_runtime.h>

#define Bc   4
#define Hc   512
#define Wc   229
#define Cc   32
#define OUTc 88
#define FRAME_ELEMS (Bc*Hc*OUTc)     /* 180224 */
#define NROW (Bc*Hc)                 /* 2048 */
#define RB   16                      /* rows per block in kernel 2 */
#define OVP  233                     /* padded ov row stride (conflict-free) */
#define KS0  115                     /* K split point */

__device__ float g_ov[NROW*Wc];       // Σ_k attn_k * nb_k per pixel
__device__ float g_wT[Wc*OUTc];       // folded linear weights, transposed [w][o]

// ---------------------------------------------------------------------------
// fast exp(d), d <= 0 : FMA-pipe exp2 poly + magic-number round
// ---------------------------------------------------------------------------
__device__ __forceinline__ float fexp_neg(float d)
{
    const float L2E   = 1.4426950408889634f;
    const float MAGIC = 12582912.0f;              // 1.5 * 2^23
    float t0 = fmaf(d, L2E, MAGIC);
    float r  = t0 - MAGIC;
    float f  = fmaf(d, L2E, -r);                  // f in [-0.5, 0.5]
    float p = 1.3333558146e-3f;
    p = fmaf(p, f, 9.6181291076e-3f);
    p = fmaf(p, f, 5.5504108665e-2f);
    p = fmaf(p, f, 2.4022650696e-1f);
    p = fmaf(p, f, 6.9314718056e-1f);
    p = fmaf(p, f, 1.0f);
    int ri = __float_as_int(t0) - 0x4B400000;     // integer round of d*log2(e)
    ri = ri < -126 ? -126 : ri;
    return p * __int_as_float((ri + 127) << 23);
}

// ---------------------------------------------------------------------------
// K1: per-(b,h)-row softmax + attn + ov. Scalars computed inline per block.
// Blocks 0..87 additionally fold W_lin -> WeffT column (tail work).
// ---------------------------------------------------------------------------
__global__ void k1(const float* __restrict__ spec,
                   const float* __restrict__ Wq,  const float* __restrict__ Wk,
                   const float* __restrict__ Wv,  const float* __restrict__ rel_t,
                   const float* __restrict__ rel_f, const float* __restrict__ W_lin,
                   float* __restrict__ out_attn)
{
    int blk = blockIdx.x;
    int b = blk >> 9, h = blk & 511;
    __shared__ float sh[3][232];            // 3 rows with +/-1 col halo
    __shared__ float sh_attn[Wc*9];         // 2061 floats
    __shared__ float s_scal[7];
    int t = threadIdx.x;

    if (t < 7) {                             // per-block scalar precompute
        if (t == 0) {
            float a = 0.f;
            #pragma unroll
            for (int c = 0; c < Cc; c++) a = fmaf(Wq[c], Wk[c], a);
            s_scal[0] = a;
        } else if (t <= 3) {
            int kt = t - 1; float r = 0.f;
            #pragma unroll
            for (int c = 0; c < 16; c++) r = fmaf(Wq[c], rel_t[c*3 + kt], r);
            s_scal[t] = r;
        } else {
            int kf = t - 4; float r = 0.f;
            #pragma unroll
            for (int c = 0; c < 16; c++) r = fmaf(Wq[16 + c], rel_f[c*3 + kf], r);
            s_scal[t] = r;
        }
    }

    for (int i = t; i < 3*231; i += 256) {   // halo tile load
        int row = i / 231, c = i % 231 - 1;
        int gh = h - 1 + row;
        float v = 0.f;
        if (gh >= 0 && gh < Hc && c >= 0 && c < Wc)
            v = spec[(b*Hc + gh)*Wc + c];
        sh[row][i % 231] = v;
    }
    __syncthreads();

    if (t < Wc) {
        const float A = s_scal[0];
        const float Rt[3] = { s_scal[1], s_scal[2], s_scal[3] };
        const float Rf[3] = { s_scal[4], s_scal[5], s_scal[6] };

        float s  = sh[1][t + 1];
        float sA = s * A;
        float nb[9], e[9];
        #pragma unroll
        for (int kt = 0; kt < 3; kt++) {
            float sr = s * Rt[kt];
            #pragma unroll
            for (int kf = 0; kf < 3; kf++) {
                float n = sh[kt][t + kf];
                nb[kt*3 + kf] = n;
                e[kt*3 + kf]  = fmaf(sA, n, fmaf(s, Rf[kf], sr));
            }
        }

        float m = e[0];
        #pragma unroll
        for (int k = 1; k < 9; k++) m = fmaxf(m, e[k]);

        float p[9], sum = 0.f;
        #pragma unroll
        for (int k = 0; k < 9; k++) { p[k] = fexp_neg(e[k] - m); sum += p[k]; }
        float rinv = __fdividef(1.f, sum);

        float ov = 0.f;
        #pragma unroll
        for (int k = 0; k < 9; k++) {
            float a = p[k] * rinv;
            sh_attn[t*9 + k] = a;
            ov = fmaf(a, nb[k], ov);
        }
        g_ov[blk*Wc + t] = ov;
    }
    __syncthreads();

    float* dst = out_attn + blk*(Wc*9);
    for (int i = t; i < Wc*9; i += 256)
        dst[i] = sh_attn[i];

    if (blk < OUTc && t < Wc) {              // fold one WeffT column
        const float* base = W_lin + blk*(Cc*Wc) + t;
        float acc = 0.f;
        #pragma unroll
        for (int c = 0; c < Cc; c++)
            acc = fmaf(base[c*Wc], Wv[c], acc);
        g_wT[t*OUTc + blk] = acc;
    }
}

// ---------------------------------------------------------------------------
// K2: frame_pred = sigmoid(ov @ Weff^T + b)
// 128 blocks x 384 threads, 16 rows/block. Two K-split groups of 176 threads
// (2 rows x 4 outs each); manual unroll-4, batched independent smem loads.
// ---------------------------------------------------------------------------
__global__ void __launch_bounds__(384, 1)
k2(const float* __restrict__ b_lin, float* __restrict__ out_frame)
{
    extern __shared__ float sm[];
    float* s_wT   = sm;                      // [229][88]
    float* s_ov   = sm + Wc*OUTc;            // [16][233]
    float* s_part = s_ov + RB*OVP;           // [176][8]
    int t  = threadIdx.x;
    int rb = blockIdx.x * RB;

    {
        const float4* src = (const float4*)g_wT;
        float4* dst = (float4*)s_wT;
        for (int i = t; i < (Wc*OUTc)/4; i += 384) dst[i] = src[i];
    }
    for (int i = t; i < RB*Wc; i += 384) {
        int r = i / Wc, w = i - r*Wc;
        s_ov[r*OVP + w] = g_ov[(rb + r)*Wc + w];
    }
    __syncthreads();

    float4 acc0 = {0.f,0.f,0.f,0.f};
    float4 acc1 = {0.f,0.f,0.f,0.f};
    int grp = 0, lt = t, rg = 0, og = 0;

    if (t < 352) {
        grp = (t >= 176);
        lt  = grp ? t - 176 : t;
        rg  = lt & 7;                        // row pair 0..7
        og  = lt >> 3;                       // out quad 0..21
        const float* wq   = s_wT + og*4;
        const float* ovr0 = s_ov + (rg*2)*OVP;
        const float* ovr1 = ovr0 + OVP;
        int w0 = grp ? KS0 : 0;
        int w1 = grp ? Wc  : KS0;

        int w = w0;
        for (; w + 4 <= w1; w += 4) {
            // batched independent loads (fill LDS pipeline)
            float4 wv0 = *(const float4*)(wq + (w+0)*OUTc);
            float4 wv1 = *(const float4*)(wq + (w+1)*OUTc);
            float4 wv2 = *(const float4*)(wq + (w+2)*OUTc);
            float4 wv3 = *(const float4*)(wq + (w+3)*OUTc);
            float a00 = ovr0[w], a01 = ovr0[w+1], a02 = ovr0[w+2], a03 = ovr0[w+3];
            float a10 = ovr1[w], a11 = ovr1[w+1], a12 = ovr1[w+2], a13 = ovr1[w+3];

            acc0.x = fmaf(a00, wv0.x, acc0.x); acc0.y = fmaf(a00, wv0.y, acc0.y);
            acc0.z = fmaf(a00, wv0.z, acc0.z); acc0.w = fmaf(a00, wv0.w, acc0.w);
            acc1.x = fmaf(a10, wv0.x, acc1.x); acc1.y = fmaf(a10, wv0.y, acc1.y);
            acc1.z = fmaf(a10, wv0.z, acc1.z); acc1.w = fmaf(a10, wv0.w, acc1.w);

            acc0.x = fmaf(a01, wv1.x, acc0.x); acc0.y = fmaf(a01, wv1.y, acc0.y);
            acc0.z = fmaf(a01, wv1.z, acc0.z); acc0.w = fmaf(a01, wv1.w, acc0.w);
            acc1.x = fmaf(a11, wv1.x, acc1.x); acc1.y = fmaf(a11, wv1.y, acc1.y);
            acc1.z = fmaf(a11, wv1.z, acc1.z); acc1.w = fmaf(a11, wv1.w, acc1.w);

            acc0.x = fmaf(a02, wv2.x, acc0.x); acc0.y = fmaf(a02, wv2.y, acc0.y);
            acc0.z = fmaf(a02, wv2.z, acc0.z); acc0.w = fmaf(a02, wv2.w, acc0.w);
            acc1.x = fmaf(a12, wv2.x, acc1.x); acc1.y = fmaf(a12, wv2.y, acc1.y);
            acc1.z = fmaf(a12, wv2.z, acc1.z); acc1.w = fmaf(a12, wv2.w, acc1.w);

            acc0.x = fmaf(a03, wv3.x, acc0.x); acc0.y = fmaf(a03, wv3.y, acc0.y);
            acc0.z = fmaf(a03, wv3.z, acc0.z); acc0.w = fmaf(a03, wv3.w, acc0.w);
            acc1.x = fmaf(a13, wv3.x, acc1.x); acc1.y = fmaf(a13, wv3.y, acc1.y);
            acc1.z = fmaf(a13, wv3.z, acc1.z); acc1.w = fmaf(a13, wv3.w, acc1.w);
        }
        for (; w < w1; w++) {
            float4 wv = *(const float4*)(wq + w*OUTc);
            float a0 = ovr0[w], a1 = ovr1[w];
            acc0.x = fmaf(a0, wv.x, acc0.x); acc0.y = fmaf(a0, wv.y, acc0.y);
            acc0.z = fmaf(a0, wv.z, acc0.z); acc0.w = fmaf(a0, wv.w, acc0.w);
            acc1.x = fmaf(a1, wv.x, acc1.x); acc1.y = fmaf(a1, wv.y, acc1.y);
            acc1.z = fmaf(a1, wv.z, acc1.z); acc1.w = fmaf(a1, wv.w, acc1.w);
        }

        if (grp) {                           // publish partial
            float* pp = s_part + lt*8;
            pp[0] = acc0.x; pp[1] = acc0.y; pp[2] = acc0.z; pp[3] = acc0.w;
            pp[4] = acc1.x; pp[5] = acc1.y; pp[6] = acc1.z; pp[7] = acc1.w;
        }
    }
    __syncthreads();

    if (t < 176) {                           // group A reduces + epilogue
        const float* pp = s_part + t*8;
        acc0.x += pp[0]; acc0.y += pp[1]; acc0.z += pp[2]; acc0.w += pp[3];
        acc1.x += pp[4]; acc1.y += pp[5]; acc1.z += pp[6]; acc1.w += pp[7];

        float4 bb = *(const float4*)&b_lin[og*4];
        float4 r0, r1;
        r0.x = __fdividef(1.f, 1.f + __expf(-(acc0.x + bb.x)));
        r0.y = __fdividef(1.f, 1.f + __expf(-(acc0.y + bb.y)));
        r0.z = __fdividef(1.f, 1.f + __expf(-(acc0.z + bb.z)));
        r0.w = __fdividef(1.f, 1.f + __expf(-(acc0.w + bb.w)));
        r1.x = __fdividef(1.f, 1.f + __expf(-(acc1.x + bb.x)));
        r1.y = __fdividef(1.f, 1.f + __expf(-(acc1.y + bb.y)));
        r1.z = __fdividef(1.f, 1.f + __expf(-(acc1.z + bb.z)));
        r1.w = __fdividef(1.f, 1.f + __expf(-(acc1.w + bb.w)));

        int row0 = rb + rg*2;
        *(float4*)&out_frame[row0*OUTc + og*4]       = r0;
        *(float4*)&out_frame[(row0 + 1)*OUTc + og*4] = r1;
    }
}

// ---------------------------------------------------------------------------
extern "C" void kernel_launch(void* const* d_in, const int* in_sizes, int n_in,
                              void* d_out, int out_size)
{
    const float* spec  = (const float*)d_in[0];
    const float* Wq    = (const float*)d_in[1];
    const float* Wk    = (const float*)d_in[2];
    const float* Wv    = (const float*)d_in[3];
    const float* rel_t = (const float*)d_in[4];
    const float* rel_f = (const float*)d_in[5];
    const float* W_lin = (const float*)d_in[6];
    const float* b_lin = (const float*)d_in[7];
    float* out = (float*)d_out;

    const int smemC = (Wc*OUTc + RB*OVP + 176*8) * (int)sizeof(float); // ~101 KB
    cudaFuncSetAttribute(k2, cudaFuncAttributeMaxDynamicSharedMemorySize, smemC);

    k1<<<NROW, 256>>>(spec, Wq, Wk, Wv, rel_t, rel_f, W_lin, out + FRAME_ELEMS);
    k2<<<NROW/RB, 384, smemC>>>(b_lin, out);
}